// round 17
// baseline (speedup 1.0000x reference)
#include <cuda_runtime.h>
#include <math.h>

#define BB 8
#define TT 200
#define UU 100
#define UU1 101
#define VV 1024
#define BLANK (VV - 1)

#define SENT (-1e30f)
#define INV_LN2 1.4426950408889634f
#define LN2     0.6931471805599453f

// scratch: per-cell blank/emit log-probs in LOG2 domain (device globals)
__device__ float g_blank_lp[BB * TT * UU1];   // [b][t][u], u in [0,U1)
__device__ float g_emit_lp[BB * TT * UU];     // [b][t][u], u in [0,U)

__device__ __forceinline__ float ex2f(float x) {
    float y; asm("ex2.approx.f32 %0, %1;" : "=f"(y) : "f"(x)); return y;
}
__device__ __forceinline__ float lg2f(float x) {
    float y; asm("lg2.approx.f32 %0, %1;" : "=f"(y) : "f"(x)); return y;
}

// ---------------------------------------------------------------------------
// Kernel 1: per-row logsumexp over V=1024, emit blank_lp / emit_lp (log2 dom).
// One warp per (b,t,u) row of 4KB. 161600 rows. HBM-bound (~94us, at SOL).
// ---------------------------------------------------------------------------
__global__ __launch_bounds__(256) void lse_kernel(
    const float* __restrict__ logits,
    const int* __restrict__ targets)
{
    const int warp = (blockIdx.x * 256 + threadIdx.x) >> 5;  // row index
    const int lane = threadIdx.x & 31;
    if (warp >= BB * TT * UU1) return;

    const int b   = warp / (TT * UU1);
    const int rem = warp % (TT * UU1);
    const int t   = rem / UU1;
    const int u   = rem % UU1;

    const float4* row4 = reinterpret_cast<const float4*>(logits) +
                         (size_t)warp * (VV / 4);

    float4 vals[8];
#pragma unroll
    for (int k = 0; k < 8; k++) vals[k] = row4[lane + 32 * k];

    float m = -INFINITY;
#pragma unroll
    for (int k = 0; k < 8; k++) {
        m = fmaxf(m, fmaxf(fmaxf(vals[k].x, vals[k].y),
                           fmaxf(vals[k].z, vals[k].w)));
    }
#pragma unroll
    for (int o = 16; o; o >>= 1) m = fmaxf(m, __shfl_xor_sync(0xffffffffu, m, o));

    float s = 0.f;
#pragma unroll
    for (int k = 0; k < 8; k++) {
        s += __expf(vals[k].x - m) + __expf(vals[k].y - m) +
             __expf(vals[k].z - m) + __expf(vals[k].w - m);
    }
#pragma unroll
    for (int o = 16; o; o >>= 1) s += __shfl_xor_sync(0xffffffffu, s, o);

    const float lse = m + __logf(s);

    if (lane == 0) {
        const float* rowf = logits + (size_t)warp * VV;
        // store in log2 domain for the DP kernel
        g_blank_lp[warp] = (rowf[BLANK] - lse) * INV_LN2;
        if (u < UU) {
            const int tgt = targets[b * UU + u];
            g_emit_lp[(b * TT + t) * UU + u] = (rowf[tgt] - lse) * INV_LN2;
        }
    }
}

// ---------------------------------------------------------------------------
// Kernel 2: register-resident skewed wavefront, ONE WARP per batch.
// Lane L owns u = 4L..4L+3; at iteration i it processes time t = i - L.
//   alpha[t][u] = LSE2(alpha[t-1][u] + blank[t-1][u],
//                      alpha[t][u-1] + emit[t][u-1])      (log2 domain)
// alpha[t-1][u] stays in this lane's registers; alpha[t][u-1] for the first
// owned cell arrives via shfl_up of the neighbor's carry (computed last iter).
// blank/emit streamed from global with a depth-3 register prefetch.
// ---------------------------------------------------------------------------

// number of pipeline iterations: must be multiple of 3, >= 199 + 25 + 1
#define NITER 225

__device__ __forceinline__ void load_iter(
    const float* __restrict__ gb, const float* __restrict__ ge,
    int t, int u0, float* B, float* E)
{
    const bool tv = (t >= 0) && (t < TT);
#pragma unroll
    for (int j = 0; j < 4; j++) {
        const int u = u0 + j;
        B[j] = (tv && t >= 1 && u <= UU) ? __ldg(gb + (t - 1) * UU1 + u) : SENT;
        E[j] = (tv && u >= 1 && u <= UU) ? __ldg(ge + t * UU + (u - 1)) : SENT;
    }
}

__global__ __launch_bounds__(32) void alpha_kernel(
    const int* __restrict__ logit_lengths,
    const int* __restrict__ target_lengths,
    float* __restrict__ out)
{
    const int b  = blockIdx.x;
    const int L  = threadIdx.x;          // lane
    const int u0 = 4 * L;

    const float* gb = g_blank_lp + (size_t)b * TT * UU1;
    const float* ge = g_emit_lp  + (size_t)b * TT * UU;

    const int t_last = logit_lengths[b] - 1;
    const int u_tl   = target_lengths[b];

    float ap[4];                         // alpha[t-1][u0+j]
#pragma unroll
    for (int j = 0; j < 4; j++) ap[j] = SENT;
    float carry = SENT;                  // alpha[t][u0+3] of my previous iter

    // depth-3 prefetch buffers (registers)
    float bl[3][4], em[3][4];
    load_iter(gb, ge, 0 - L, u0, bl[0], em[0]);
    load_iter(gb, ge, 1 - L, u0, bl[1], em[1]);
    load_iter(gb, ge, 2 - L, u0, bl[2], em[2]);

    for (int i = 0; i < NITER; i += 3) {
#pragma unroll
        for (int s = 0; s < 3; s++) {
            const int t = i + s - L;
            const bool tv = (t >= 0) & (t < TT);

            float left = __shfl_up_sync(0xffffffffu, carry, 1);
            if (L == 0) left = SENT;

            float* B = bl[s];
            float* E = em[s];

#pragma unroll
            for (int j = 0; j < 4; j++) {
                const int u = u0 + j;
                const float a  = ap[j] + B[j];
                const float bv = left  + E[j];
                const float mx = fmaxf(a, bv);
                const float mn = fminf(a, bv);
                float nv = mx + lg2f(1.0f + ex2f(mn - mx));
                if (!tv | (u > UU)) nv = SENT;
                if ((t == 0) & (u == 0)) nv = 0.0f;
                if ((t == t_last) & (u == u_tl)) {
                    const float fb = __ldg(gb + t_last * UU1 + u_tl);
                    out[b] = -(nv + fb) * LN2;
                }
                ap[j] = nv;
                left  = nv;
            }
            carry = left;

            // refill this slot for iteration i+s+3 (~700 cyc of lead)
            load_iter(gb, ge, t + 3, u0, B, E);
        }
    }
}

// ---------------------------------------------------------------------------
extern "C" void kernel_launch(void* const* d_in, const int* in_sizes, int n_in,
                              void* d_out, int out_size)
{
    const float* logits         = (const float*)d_in[0];
    const int*   targets        = (const int*)d_in[1];
    const int*   logit_lengths  = (const int*)d_in[2];
    const int*   target_lengths = (const int*)d_in[3];
    float* out = (float*)d_out;

    const int rows   = BB * TT * UU1;
    const int blocks = (rows + 7) / 8;   // 8 warps per 256-thread block
    lse_kernel<<<blocks, 256>>>(logits, targets);

    alpha_kernel<<<BB, 32>>>(logit_lengths, target_lengths, out);
}